// round 13
// baseline (speedup 1.0000x reference)
#include <cuda_runtime.h>
#include <stdint.h>

// XNOR binarized linear — R12 champion (streaming cache ops) + row-pair
// processing for 2x memory-level parallelism.
// y[n,o] = (256 - 2*popc(xbits[n] ^ wbits[o])) * scale[o]
//
// R12 (ldcs/stcs) lifted BW 3.18->3.79 TB/s; remaining gap is MLP: 1KB/warp
// in flight vs ~25KB/SM needed. This version prefetches a ROW PAIR (2KB/warp,
// 32KB/SM at 16 warps) while computing the current pair. Everything else
// (warp-broadcast ballots, weights in regs, exact magic epilogue) unchanged.

constexpr int NROWS = 262144;
constexpr int DIM   = 256;   // IN == OUT
constexpr int WPR   = 8;     // packed words per row

constexpr int CHUNK_ROWS = 128;                 // rows per block (4 warps x 32)
constexpr int NBLOCKS    = NROWS / CHUNK_ROWS;  // 2048, one chunk per block

__device__ uint32_t g_wbits[DIM * WPR];

// ---------------------------------------------------------------------------
// Pre-kernel: pack weight sign bits (one warp per output row).
// Word (h*4+c), bit L  <->  element h*128 + 4L + c. Matches x packing below.
// ---------------------------------------------------------------------------
__global__ void pack_w_kernel(const float* __restrict__ w) {
    int warp = (blockIdx.x * blockDim.x + threadIdx.x) >> 5;
    int lane = threadIdx.x & 31;
    if (warp >= DIM) return;
    const float4* row = reinterpret_cast<const float4*>(w) + (size_t)warp * (DIM / 4);
#pragma unroll
    for (int h = 0; h < 2; ++h) {
        float4 v = row[h * 32 + lane];
        uint32_t m0 = __ballot_sync(0xFFFFFFFFu, v.x < 0.0f);
        uint32_t m1 = __ballot_sync(0xFFFFFFFFu, v.y < 0.0f);
        uint32_t m2 = __ballot_sync(0xFFFFFFFFu, v.z < 0.0f);
        uint32_t m3 = __ballot_sync(0xFFFFFFFFu, v.w < 0.0f);
        if (lane == 0) {
            *reinterpret_cast<uint4*>(&g_wbits[warp * WPR + h * 4]) =
                make_uint4(m0, m1, m2, m3);
        }
    }
}

// ---------------------------------------------------------------------------
// Main kernel: 128 threads (4 warps), one 128-row chunk per block.
// Each warp: 32 rows, processed as 16 row-pairs with pair-ahead prefetch.
// ---------------------------------------------------------------------------
__global__ void __launch_bounds__(128, 4)
xnor_pair_kernel(const float* __restrict__ x,
                 const float* __restrict__ scale,
                 float* __restrict__ out) {
    const int warp = threadIdx.x >> 5;
    const int lane = threadIdx.x & 31;

    // Hoist weights + scale for this lane's 8 output columns (strided o=32j+L).
    uint4 wlo[8], whi[8];
    float S[8];
#pragma unroll
    for (int j = 0; j < 8; ++j) {
        int o = j * 32 + lane;
        wlo[j] = *reinterpret_cast<const uint4*>(&g_wbits[o * WPR]);
        whi[j] = *reinterpret_cast<const uint4*>(&g_wbits[o * WPR + 4]);
        S[j] = scale[o];
    }

    constexpr uint32_t MAGIC256 = 0x4B400000u + 256u;   // 2^23*1.5 + 256

    const int row0 = blockIdx.x * CHUNK_ROWS + warp * 32;
    const float4* rp = reinterpret_cast<const float4*>(x) +
                       (size_t)row0 * (DIM / 4);
    float* orow = out + (size_t)row0 * DIM + lane;

    // prefetch first row pair (streaming loads: evict-first)
    float4 c0 = __ldcs(&rp[lane]);        float4 c1 = __ldcs(&rp[32 + lane]);
    float4 d0 = __ldcs(&rp[64 + lane]);   float4 d1 = __ldcs(&rp[96 + lane]);

#pragma unroll 2
    for (int r = 0; r < 32; r += 2) {
        // issue next pair's loads (clamped on last iteration)
        const float4* np = rp + (size_t)(r + 2 < 32 ? r + 2 : 30) * (DIM / 4);
        float4 e0 = __ldcs(&np[lane]);        float4 e1 = __ldcs(&np[32 + lane]);
        float4 f0 = __ldcs(&np[64 + lane]);   float4 f1 = __ldcs(&np[96 + lane]);

        // ballot-transpose both rows' sign bits (broadcast to all lanes)
        uint32_t a0 = __ballot_sync(0xFFFFFFFFu, c0.x < 0.0f);
        uint32_t a1 = __ballot_sync(0xFFFFFFFFu, c0.y < 0.0f);
        uint32_t a2 = __ballot_sync(0xFFFFFFFFu, c0.z < 0.0f);
        uint32_t a3 = __ballot_sync(0xFFFFFFFFu, c0.w < 0.0f);
        uint32_t a4 = __ballot_sync(0xFFFFFFFFu, c1.x < 0.0f);
        uint32_t a5 = __ballot_sync(0xFFFFFFFFu, c1.y < 0.0f);
        uint32_t a6 = __ballot_sync(0xFFFFFFFFu, c1.z < 0.0f);
        uint32_t a7 = __ballot_sync(0xFFFFFFFFu, c1.w < 0.0f);

        uint32_t g0 = __ballot_sync(0xFFFFFFFFu, d0.x < 0.0f);
        uint32_t g1 = __ballot_sync(0xFFFFFFFFu, d0.y < 0.0f);
        uint32_t g2 = __ballot_sync(0xFFFFFFFFu, d0.z < 0.0f);
        uint32_t g3 = __ballot_sync(0xFFFFFFFFu, d0.w < 0.0f);
        uint32_t g4 = __ballot_sync(0xFFFFFFFFu, d1.x < 0.0f);
        uint32_t g5 = __ballot_sync(0xFFFFFFFFu, d1.y < 0.0f);
        uint32_t g6 = __ballot_sync(0xFFFFFFFFu, d1.z < 0.0f);
        uint32_t g7 = __ballot_sync(0xFFFFFFFFu, d1.w < 0.0f);

        // row r: 8 output groups
#pragma unroll
        for (int j = 0; j < 8; ++j) {
            int p = __popc(a0 ^ wlo[j].x) + __popc(a1 ^ wlo[j].y) +
                    __popc(a2 ^ wlo[j].z) + __popc(a3 ^ wlo[j].w) +
                    __popc(a4 ^ whi[j].x) + __popc(a5 ^ whi[j].y) +
                    __popc(a6 ^ whi[j].z) + __popc(a7 ^ whi[j].w);
            uint32_t t = MAGIC256 - 2u * (uint32_t)p;       // IMAD
            float fd = __uint_as_float(t) - 12582912.0f;    // FADD (exact)
            __stcs(&orow[j * 32], fd * S[j]);               // streaming STG
        }
        // row r+1: 8 output groups
#pragma unroll
        for (int j = 0; j < 8; ++j) {
            int p = __popc(g0 ^ wlo[j].x) + __popc(g1 ^ wlo[j].y) +
                    __popc(g2 ^ wlo[j].z) + __popc(g3 ^ wlo[j].w) +
                    __popc(g4 ^ whi[j].x) + __popc(g5 ^ whi[j].y) +
                    __popc(g6 ^ whi[j].z) + __popc(g7 ^ whi[j].w);
            uint32_t t = MAGIC256 - 2u * (uint32_t)p;
            float fd = __uint_as_float(t) - 12582912.0f;
            __stcs(&orow[DIM + j * 32], fd * S[j]);
        }

        c0 = e0; c1 = e1; d0 = f0; d1 = f1;
        orow += 2 * DIM;
    }
}

// ---------------------------------------------------------------------------
// kernel_launch: d_in[0]=x [N,256] f32, d_in[1]=weight [256,256] f32,
//                d_in[2]=scale [1,256] f32; d_out = y [N,256] f32.
// ---------------------------------------------------------------------------
extern "C" void kernel_launch(void* const* d_in, const int* in_sizes, int n_in,
                              void* d_out, int out_size) {
    const float* x      = (const float*)d_in[0];
    const float* weight = (const float*)d_in[1];
    const float* scale  = (const float*)d_in[2];
    float* out          = (float*)d_out;
    (void)in_sizes; (void)n_in; (void)out_size;

    pack_w_kernel<<<32, 256>>>(weight);
    xnor_pair_kernel<<<NBLOCKS, 128>>>(x, scale, out);
}

// round 14
// speedup vs baseline: 1.1004x; 1.1004x over previous
#include <cuda_runtime.h>
#include <stdint.h>

// XNOR binarized linear — R12 champion + L2 software prefetch (register-free MLP).
// y[n,o] = (256 - 2*popc(xbits[n] ^ wbits[o])) * scale[o]
//
// R12 (ldcs/stcs): 131us, DRAM 47.8%. Reads are DRAM-latency bound with only
// 16KB/SM in flight; register-based deepening (R13) regressed at the 128-reg
// ceiling. Fix: prefetch.global.L2 for row r+6 (address-only, no regs, no
// scoreboard) so the demand ldcs mostly hits L2 (~250cyc), which 16 warps of
// depth-1 register prefetch can cover.

constexpr int NROWS = 262144;
constexpr int DIM   = 256;   // IN == OUT
constexpr int WPR   = 8;     // packed words per row

constexpr int CHUNK_ROWS = 128;                 // rows per block (4 warps x 32)
constexpr int NBLOCKS    = NROWS / CHUNK_ROWS;  // 2048, one chunk per block

constexpr int PF_DIST = 6;                      // prefetch lead (rows)

__device__ uint32_t g_wbits[DIM * WPR];

__device__ __forceinline__ void prefetch_l2(const void* p) {
    asm volatile("prefetch.global.L2 [%0];" :: "l"(p));
}

// ---------------------------------------------------------------------------
// Pre-kernel: pack weight sign bits (one warp per output row).
// Word (h*4+c), bit L  <->  element h*128 + 4L + c. Matches x packing below.
// ---------------------------------------------------------------------------
__global__ void pack_w_kernel(const float* __restrict__ w) {
    int warp = (blockIdx.x * blockDim.x + threadIdx.x) >> 5;
    int lane = threadIdx.x & 31;
    if (warp >= DIM) return;
    const float4* row = reinterpret_cast<const float4*>(w) + (size_t)warp * (DIM / 4);
#pragma unroll
    for (int h = 0; h < 2; ++h) {
        float4 v = row[h * 32 + lane];
        uint32_t m0 = __ballot_sync(0xFFFFFFFFu, v.x < 0.0f);
        uint32_t m1 = __ballot_sync(0xFFFFFFFFu, v.y < 0.0f);
        uint32_t m2 = __ballot_sync(0xFFFFFFFFu, v.z < 0.0f);
        uint32_t m3 = __ballot_sync(0xFFFFFFFFu, v.w < 0.0f);
        if (lane == 0) {
            *reinterpret_cast<uint4*>(&g_wbits[warp * WPR + h * 4]) =
                make_uint4(m0, m1, m2, m3);
        }
    }
}

// ---------------------------------------------------------------------------
// Main kernel: 128 threads (4 warps), one 128-row chunk per block.
// ---------------------------------------------------------------------------
__global__ void __launch_bounds__(128, 4)
xnor_pf_kernel(const float* __restrict__ x,
               const float* __restrict__ scale,
               float* __restrict__ out) {
    const int warp = threadIdx.x >> 5;
    const int lane = threadIdx.x & 31;

    // Hoist weights + scale for this lane's 8 output columns (strided o=32j+L).
    uint4 wlo[8], whi[8];
    float S[8];
#pragma unroll
    for (int j = 0; j < 8; ++j) {
        int o = j * 32 + lane;
        wlo[j] = *reinterpret_cast<const uint4*>(&g_wbits[o * WPR]);
        whi[j] = *reinterpret_cast<const uint4*>(&g_wbits[o * WPR + 4]);
        S[j] = scale[o];
    }

    constexpr uint32_t MAGIC256 = 0x4B400000u + 256u;   // 2^23*1.5 + 256

    const int row0 = blockIdx.x * CHUNK_ROWS + warp * 32;
    const float4* rp = reinterpret_cast<const float4*>(x) +
                       (size_t)row0 * (DIM / 4);
    float* orow = out + (size_t)row0 * DIM + lane;

    // warm the L2 prefetch pipeline for the first PF_DIST rows
#pragma unroll
    for (int r = 1; r < PF_DIST; ++r) {
        prefetch_l2(&rp[r * 64 + lane]);
        prefetch_l2(&rp[r * 64 + 32 + lane]);
    }

    // prefetch first row into registers (streaming: evict-first)
    float4 c0 = __ldcs(&rp[lane]);
    float4 c1 = __ldcs(&rp[32 + lane]);

#pragma unroll 2
    for (int r = 0; r < 32; ++r) {
        // L2 prefetch for row r+PF_DIST (clamped)
        const int rf = (r + PF_DIST < 32) ? r + PF_DIST : 31;
        prefetch_l2(&rp[rf * 64 + lane]);
        prefetch_l2(&rp[rf * 64 + 32 + lane]);

        // register prefetch next row (clamped on last iteration)
        const float4* np = rp + (size_t)(r + 1 < 32 ? r + 1 : r) * (DIM / 4);
        float4 n0 = __ldcs(&np[lane]);
        float4 n1 = __ldcs(&np[32 + lane]);

        // transpose row signs into 8 words, broadcast to all lanes
        uint32_t b0 = __ballot_sync(0xFFFFFFFFu, c0.x < 0.0f);
        uint32_t b1 = __ballot_sync(0xFFFFFFFFu, c0.y < 0.0f);
        uint32_t b2 = __ballot_sync(0xFFFFFFFFu, c0.z < 0.0f);
        uint32_t b3 = __ballot_sync(0xFFFFFFFFu, c0.w < 0.0f);
        uint32_t b4 = __ballot_sync(0xFFFFFFFFu, c1.x < 0.0f);
        uint32_t b5 = __ballot_sync(0xFFFFFFFFu, c1.y < 0.0f);
        uint32_t b6 = __ballot_sync(0xFFFFFFFFu, c1.z < 0.0f);
        uint32_t b7 = __ballot_sync(0xFFFFFFFFu, c1.w < 0.0f);

        // 8 independent output-group chains (ILP)
#pragma unroll
        for (int j = 0; j < 8; ++j) {
            int p = __popc(b0 ^ wlo[j].x) + __popc(b1 ^ wlo[j].y) +
                    __popc(b2 ^ wlo[j].z) + __popc(b3 ^ wlo[j].w) +
                    __popc(b4 ^ whi[j].x) + __popc(b5 ^ whi[j].y) +
                    __popc(b6 ^ whi[j].z) + __popc(b7 ^ whi[j].w);
            // exact: t = magic + (256-2p); fd = float(256-2p) exactly
            uint32_t t = MAGIC256 - 2u * (uint32_t)p;       // IMAD
            float fd = __uint_as_float(t) - 12582912.0f;    // FADD (exact)
            __stcs(&orow[j * 32], fd * S[j]);               // streaming STG
        }

        c0 = n0; c1 = n1;
        orow += DIM;
    }
}

// ---------------------------------------------------------------------------
// kernel_launch: d_in[0]=x [N,256] f32, d_in[1]=weight [256,256] f32,
//                d_in[2]=scale [1,256] f32; d_out = y [N,256] f32.
// ---------------------------------------------------------------------------
extern "C" void kernel_launch(void* const* d_in, const int* in_sizes, int n_in,
                              void* d_out, int out_size) {
    const float* x      = (const float*)d_in[0];
    const float* weight = (const float*)d_in[1];
    const float* scale  = (const float*)d_in[2];
    float* out          = (float*)d_out;
    (void)in_sizes; (void)n_in; (void)out_size;

    pack_w_kernel<<<32, 256>>>(weight);
    xnor_pf_kernel<<<NBLOCKS, 128>>>(x, scale, out);
}